// round 14
// baseline (speedup 1.0000x reference)
#include <cuda_runtime.h>
#include <cuda_bf16.h>
#include <math.h>
#include <stdint.h>

#define Bb 256
#define Tt 200
#define Nh 8
#define Dd 64
#define MODEL 512
#define FFNH 2048
#define ROWS (Bb*Tt)            // 51200
#define EPSV 1.1920929e-07f

// ---------------- scratch (static device globals) ------------------------------
__device__ __nv_bfloat16 d_snb[(size_t)ROWS * MODEL];   // rmsnorm output (bf16)
__device__ __nv_bfloat16 d_g [(size_t)ROWS * FFNH];     // gated FFN activation (bf16)
__device__ __nv_bfloat16 d_hb[(size_t)ROWS * MODEL];    // FFN output + residual (bf16)
__device__ __nv_bfloat16 d_w1b[MODEL * FFNH];
__device__ __nv_bfloat16 d_w2b[MODEL * FFNH];
__device__ __nv_bfloat16 d_w3b[FFNH * MODEL];

// ---------------- PTX helpers ----------------------------------------------------
__device__ __forceinline__ uint32_t smem_u32(const void* p) {
    uint32_t a;
    asm("{ .reg .u64 t; cvta.to.shared.u64 t, %1; cvt.u32.u64 %0, t; }" : "=r"(a) : "l"(p));
    return a;
}
#define CP_ASYNC(dst, src) asm volatile("cp.async.cg.shared.global [%0], [%1], 16;" :: "r"(dst), "l"(src))
#define CP_COMMIT()        asm volatile("cp.async.commit_group;" ::: "memory")
#define CP_WAIT1()         asm volatile("cp.async.wait_group 1;" ::: "memory")

#define LDMX4(r, addr) asm volatile( \
    "ldmatrix.sync.aligned.m8n8.x4.shared.b16 {%0,%1,%2,%3}, [%4];" \
    : "=r"((r)[0]), "=r"((r)[1]), "=r"((r)[2]), "=r"((r)[3]) : "r"(addr))
#define LDMX4T(r, addr) asm volatile( \
    "ldmatrix.sync.aligned.m8n8.x4.trans.shared.b16 {%0,%1,%2,%3}, [%4];" \
    : "=r"((r)[0]), "=r"((r)[1]), "=r"((r)[2]), "=r"((r)[3]) : "r"(addr))

__device__ __forceinline__ void mma_bf16(float* c, const uint32_t* a, const uint32_t* b) {
    asm volatile(
        "mma.sync.aligned.m16n8k16.row.col.f32.bf16.bf16.f32 "
        "{%0,%1,%2,%3}, {%4,%5,%6,%7}, {%8,%9}, {%0,%1,%2,%3};"
        : "+f"(c[0]), "+f"(c[1]), "+f"(c[2]), "+f"(c[3])
        : "r"(a[0]), "r"(a[1]), "r"(a[2]), "r"(a[3]), "r"(b[0]), "r"(b[1]));
}

// ================================================================================
// prep: pack w1/w2/w3 fp32->bf16  +  rmsnorm(seq)->bf16, ONE launch
// ================================================================================
__global__ __launch_bounds__(256) void prep_kernel(
    const float* __restrict__ w1, const float* __restrict__ w2,
    const float* __restrict__ w3, const float* __restrict__ seq,
    const float* __restrict__ rmsw,
    __nv_bfloat16* __restrict__ w1b, __nv_bfloat16* __restrict__ w2b,
    __nv_bfloat16* __restrict__ w3b, __nv_bfloat16* __restrict__ snb)
{
    const int bx = blockIdx.x;
    if (bx < 3072) {
        const int wsel = bx >> 10;          // 0,1,2
        const int i = (bx & 1023) * 256 + threadIdx.x;   // float4 index
        const float* src = (wsel == 0) ? w1 : (wsel == 1) ? w2 : w3;
        __nv_bfloat16* dst = (wsel == 0) ? w1b : (wsel == 1) ? w2b : w3b;
        const float4 v = ((const float4*)src)[i];
        __nv_bfloat162 lo = __floats2bfloat162_rn(v.x, v.y);
        __nv_bfloat162 hi = __floats2bfloat162_rn(v.z, v.w);
        uint2 st;
        st.x = *(uint32_t*)&lo;
        st.y = *(uint32_t*)&hi;
        ((uint2*)dst)[i] = st;
    } else {
        const int lane = threadIdx.x & 31;
        const int row = (bx - 3072) * 8 + (threadIdx.x >> 5);
        const float4* x = (const float4*)(seq + (size_t)row * MODEL);
        float4 xv[4];
        float s = 0.f;
        #pragma unroll
        for (int i = 0; i < 4; i++) {
            xv[i] = x[lane + 32*i];
            s += xv[i].x*xv[i].x + xv[i].y*xv[i].y + xv[i].z*xv[i].z + xv[i].w*xv[i].w;
        }
        #pragma unroll
        for (int off = 16; off; off >>= 1) s += __shfl_xor_sync(0xffffffffu, s, off);
        const float inv = rsqrtf(s * (1.0f / MODEL) + EPSV);
        const float4* wp = (const float4*)rmsw;
        #pragma unroll
        for (int i = 0; i < 4; i++) {
            const float4 wv = wp[lane + 32*i];
            __nv_bfloat162 o0 = __floats2bfloat162_rn(xv[i].x*inv*wv.x, xv[i].y*inv*wv.y);
            __nv_bfloat162 o1 = __floats2bfloat162_rn(xv[i].z*inv*wv.z, xv[i].w*inv*wv.w);
            uint2 st;
            st.x = *(uint32_t*)&o0;
            st.y = *(uint32_t*)&o1;
            ((uint2*)(snb + (size_t)row * MODEL))[lane + 32*i] = st;
        }
    }
}

// ================================================================================
// GEMM1: G = bf16( silu(A@W1) * (A@W2) )  — PDL consumer of prep
// ================================================================================
__global__ void __launch_bounds__(256, 2) gemm_fused_kernel(
    const __nv_bfloat16* __restrict__ A, const __nv_bfloat16* __restrict__ W1,
    const __nv_bfloat16* __restrict__ W2, __nv_bfloat16* __restrict__ G)
{
    extern __shared__ char sm[];
    const uint32_t sb = smem_u32(sm);
    const int tid = threadIdx.x;
    const int wid = tid >> 5, lane = tid & 31;
    const int wm = (wid >> 2) * 64, wn = (wid & 3) * 16;
    const int m0 = blockIdx.y * 128, n0 = blockIdx.x * 64;

    float accX[4][2][4], accG[4][2][4];
    #pragma unroll
    for (int i = 0; i < 4; i++)
        #pragma unroll
        for (int j = 0; j < 2; j++)
            #pragma unroll
            for (int v = 0; v < 4; v++) { accX[i][j][v] = 0.f; accG[i][j][v] = 0.f; }

    auto issue = [&](int st, int k0) {
        const uint32_t sA  = sb + (uint32_t)st*16384u;
        const uint32_t sB1 = sb + 49152u + (uint32_t)st*8192u;
        const uint32_t sB2 = sb + 73728u + (uint32_t)st*8192u;
        const int arow = tid >> 1;
        const __nv_bfloat16* ag = A + (size_t)(m0 + arow)*MODEL + k0 + (tid & 1)*32;
        const uint32_t abase = sA + (uint32_t)arow*128u;
        #pragma unroll
        for (int j = 0; j < 4; j++) {
            const int c = (tid & 1)*4 + j;
            CP_ASYNC(abase + (uint32_t)((c ^ (arow & 7)) << 4), ag + j*8);
        }
        const int brow = tid >> 2;
        const __nv_bfloat16* b1g = W1 + (size_t)(k0 + brow)*FFNH + n0 + (tid & 3)*16;
        const __nv_bfloat16* b2g = W2 + (size_t)(k0 + brow)*FFNH + n0 + (tid & 3)*16;
        const uint32_t b1base = sB1 + (uint32_t)brow*128u;
        const uint32_t b2base = sB2 + (uint32_t)brow*128u;
        #pragma unroll
        for (int j = 0; j < 2; j++) {
            const int c = (tid & 3)*2 + j;
            const uint32_t sw = (uint32_t)((c ^ (brow & 7)) << 4);
            CP_ASYNC(b1base + sw, b1g + j*8);
            CP_ASYNC(b2base + sw, b2g + j*8);
        }
        CP_COMMIT();
    };

    // wait for prep (snb / w1b / w2b ready)
    cudaGridDependencySynchronize();

    const int NT = MODEL / 64;  // 8
    issue(0, 0);
    issue(1, 64);

    auto step = [&](int kt, int cur, int nxt) {
        CP_WAIT1();
        __syncthreads();
        if (kt + 2 < NT) issue(nxt, (kt + 2)*64); else CP_COMMIT();

        const uint32_t sA  = sb + (uint32_t)cur*16384u;
        const uint32_t sB1 = sb + 49152u + (uint32_t)cur*8192u;
        const uint32_t sB2 = sb + 73728u + (uint32_t)cur*8192u;

        #pragma unroll
        for (int k16 = 0; k16 < 4; ++k16) {
            uint32_t af[4][4];
            #pragma unroll
            for (int mt = 0; mt < 4; mt++) {
                const int row = wm + mt*16 + (lane & 15);
                const uint32_t a = sA + (uint32_t)row*128u
                    + (uint32_t)((((k16*2 + (lane >> 4)) ^ (row & 7))) << 4);
                LDMX4(af[mt], a);
            }
            uint32_t b1[4], b2[4];
            {
                const int krow = k16*16 + (lane & 15);
                const int nch = (wid & 3)*2 + (lane >> 4);
                const uint32_t off = (uint32_t)krow*128u + (uint32_t)((nch ^ (lane & 7)) << 4);
                LDMX4T(b1, sB1 + off);
                LDMX4T(b2, sB2 + off);
            }
            #pragma unroll
            for (int mt = 0; mt < 4; mt++)
                #pragma unroll
                for (int nt = 0; nt < 2; nt++) {
                    mma_bf16(accX[mt][nt], af[mt], &b1[nt*2]);
                    mma_bf16(accG[mt][nt], af[mt], &b2[nt*2]);
                }
        }
    };

    for (int kt0 = 0; kt0 < NT; kt0 += 3) {
        step(kt0, 0, 2);
        if (kt0 + 1 < NT) step(kt0 + 1, 1, 0);
        if (kt0 + 2 < NT) step(kt0 + 2, 2, 1);
    }

    cudaTriggerProgrammaticLaunchCompletion();

    // epilogue: silu(X)*G -> bf16x2
    const int r = lane >> 2, q = lane & 3;
    #pragma unroll
    for (int mt = 0; mt < 4; mt++) {
        #pragma unroll
        for (int nt = 0; nt < 2; nt++) {
            const int col = n0 + wn + nt*8 + 2*q;
            #pragma unroll
            for (int half = 0; half < 2; half++) {
                const int row = m0 + wm + mt*16 + r + half*8;
                const float x0 = accX[mt][nt][half*2 + 0], g0 = accG[mt][nt][half*2 + 0];
                const float x1 = accX[mt][nt][half*2 + 1], g1 = accG[mt][nt][half*2 + 1];
                const float o0 = x0 / (1.f + __expf(-x0)) * g0;
                const float o1 = x1 / (1.f + __expf(-x1)) * g1;
                __nv_bfloat162 st = __floats2bfloat162_rn(o0, o1);
                *(__nv_bfloat162*)(G + (size_t)row*FFNH + col) = st;
            }
        }
    }
}

// ================================================================================
// GEMM2: H = bf16(A@W3 + seq) — 128x128 tile, PDL consumer of GEMM1
// ================================================================================
__global__ void __launch_bounds__(256, 2) gemm_out_kernel(
    const __nv_bfloat16* __restrict__ A, const __nv_bfloat16* __restrict__ W3,
    const float* __restrict__ seq, __nv_bfloat16* __restrict__ H)
{
    extern __shared__ char sm[];
    const uint32_t sb = smem_u32(sm);
    const int tid = threadIdx.x;
    const int wid = tid >> 5, lane = tid & 31;
    const int wm = (wid >> 2) * 64, wn = (wid & 3) * 32;
    const int m0 = blockIdx.y * 128, n0 = blockIdx.x * 128;

    float acc[4][4][4];
    #pragma unroll
    for (int i = 0; i < 4; i++)
        #pragma unroll
        for (int j = 0; j < 4; j++)
            #pragma unroll
            for (int v = 0; v < 4; v++) acc[i][j][v] = 0.f;

    auto issue = [&](int st, int k0) {
        const uint32_t sA = sb + (uint32_t)st*16384u;
        const uint32_t sB = sb + 49152u + (uint32_t)st*16384u;
        const int arow = tid >> 1;
        const __nv_bfloat16* ag = A + (size_t)(m0 + arow)*FFNH + k0 + (tid & 1)*32;
        const uint32_t abase = sA + (uint32_t)arow*128u;
        #pragma unroll
        for (int j = 0; j < 4; j++) {
            const int c = (tid & 1)*4 + j;
            CP_ASYNC(abase + (uint32_t)((c ^ (arow & 7)) << 4), ag + j*8);
        }
        const int brow = tid >> 2;
        const __nv_bfloat16* bg = W3 + (size_t)(k0 + brow)*MODEL + n0 + (tid & 3)*32;
        const uint32_t bbase = sB + (uint32_t)brow*256u;
        #pragma unroll
        for (int j = 0; j < 4; j++) {
            const int c = (tid & 3)*4 + j;
            CP_ASYNC(bbase + (uint32_t)((c ^ (brow & 7)) << 4), bg + j*8);
        }
        CP_COMMIT();
    };

    // wait for GEMM1 completion (A = g)
    cudaGridDependencySynchronize();

    const int NT = FFNH / 64;  // 32
    issue(0, 0);
    issue(1, 64);

    auto step = [&](int kt, int cur, int nxt) {
        CP_WAIT1();
        __syncthreads();
        if (kt + 2 < NT) issue(nxt, (kt + 2)*64); else CP_COMMIT();

        const uint32_t sA = sb + (uint32_t)cur*16384u;
        const uint32_t sB = sb + 49152u + (uint32_t)cur*16384u;

        #pragma unroll
        for (int k16 = 0; k16 < 4; ++k16) {
            uint32_t af[4][4];
            #pragma unroll
            for (int mt = 0; mt < 4; mt++) {
                const int row = wm + mt*16 + (lane & 15);
                const uint32_t a = sA + (uint32_t)row*128u
                    + (uint32_t)((((k16*2 + (lane >> 4)) ^ (row & 7))) << 4);
                LDMX4(af[mt], a);
            }
            uint32_t bf[8];
            {
                const int krow = k16*16 + (lane & 15);
                const uint32_t rowoff = (uint32_t)krow*256u;
                #pragma unroll
                for (int hh = 0; hh < 2; hh++) {
                    const int nch = (wid & 3)*4 + hh*2 + (lane >> 4);
                    LDMX4T(&bf[hh*4], sB + rowoff + (uint32_t)((nch ^ (lane & 7)) << 4));
                }
            }
            #pragma unroll
            for (int mt = 0; mt < 4; mt++)
                #pragma unroll
                for (int nt = 0; nt < 4; nt++)
                    mma_bf16(acc[mt][nt], af[mt], &bf[nt*2]);
        }
    };

    for (int kt0 = 0; kt0 < NT; kt0 += 3) {
        step(kt0, 0, 2);
        if (kt0 + 1 < NT) step(kt0 + 1, 1, 0);
        if (kt0 + 2 < NT) step(kt0 + 2, 2, 1);
    }

    cudaTriggerProgrammaticLaunchCompletion();

    // epilogue: + seq residual -> bf16
    const int r = lane >> 2, q = lane & 3;
    #pragma unroll
    for (int mt = 0; mt < 4; mt++) {
        #pragma unroll
        for (int nt = 0; nt < 4; nt++) {
            const int col = n0 + wn + nt*8 + 2*q;
            #pragma unroll
            for (int half = 0; half < 2; half++) {
                const int row = m0 + wm + mt*16 + r + half*8;
                const float2 s = *(const float2*)(seq + (size_t)row*MODEL + col);
                __nv_bfloat162 st = __floats2bfloat162_rn(
                    acc[mt][nt][half*2 + 0] + s.x,
                    acc[mt][nt][half*2 + 1] + s.y);
                *(__nv_bfloat162*)(H + (size_t)row*MODEL + col) = st;
            }
        }
    }
}

// ================================================================================
// fused single-query attention — bf16 h; 8 lanes per row score phase (1 line/instr)
// ================================================================================
__global__ __launch_bounds__(128) void attn_kernel(
    const float* __restrict__ q, const __nv_bfloat16* __restrict__ h,
    const float* __restrict__ wk, const float* __restrict__ wv,
    const void* __restrict__ mask, float* __restrict__ out)
{
    const int n = blockIdx.x;
    const int b = blockIdx.y;
    const int tid = threadIdx.x;
    const int lane = tid & 31, warp = tid >> 5;

    __shared__ float q_s[64], qk_s[64], s_s[Tt], u_part[4][64], red[4];
    __shared__ int mz[4];

    // ---- pre-sync work: independent of h (mask, q, w_k @ q) ----
    int nz = 0;
    if (tid < 64) {
        const unsigned char* mb = (const unsigned char*)mask;
        nz = mb[4*tid + 1] | mb[4*tid + 2] | mb[4*tid + 3];
    }
    const int wany = __any_sync(0xffffffffu, nz != 0) ? 1 : 0;
    if (lane == 0) mz[warp] = wany;

    if (tid < 64) q_s[tid] = q[((size_t)b*Nh + n)*Dd + tid];
    __syncthreads();

    const int mask_int = !(mz[0] | mz[1]);

    if (tid < 64) {
        const float4* wkp = (const float4*)(wk + ((size_t)n*Dd + tid)*Dd);
        float a0 = 0.f, a1 = 0.f;
        #pragma unroll 8
        for (int e = 0; e < 16; e++) {
            const float4 v = wkp[e];
            a0 = fmaf(v.x, q_s[4*e+0], a0);
            a1 = fmaf(v.y, q_s[4*e+1], a1);
            a0 = fmaf(v.z, q_s[4*e+2], a0);
            a1 = fmaf(v.w, q_s[4*e+3], a1);
        }
        qk_s[tid] = a0 + a1;
    }
    __syncthreads();

    // ---- wait for GEMM2 (h ready) ----
    cudaGridDependencySynchronize();

    const float scale = 0.125f;

    // scores: 8 lanes per row, uint4 = 8 bf16 each -> one 128B line per warp instr
    {
        const int sub = lane >> 3;     // 0..3 (4 rows per warp)
        const int ln8 = lane & 7;
        float qv[8];
        #pragma unroll
        for (int j = 0; j < 8; j++) qv[j] = qk_s[ln8*8 + j];
        for (int t0 = warp*4 + sub; t0 < Tt; t0 += 16) {
            const uint4 raw = *(const uint4*)(h + ((size_t)(b*Tt + t0))*MODEL + n*Dd + ln8*8);
            const __nv_bfloat162* pr = (const __nv_bfloat162*)&raw;
            float p = 0.f;
            #pragma unroll
            for (int j = 0; j < 4; j++) {
                const float2 f = __bfloat1622float2(pr[j]);
                p = fmaf(f.x, qv[2*j],   p);
                p = fmaf(f.y, qv[2*j+1], p);
            }
            p += __shfl_xor_sync(0xffffffffu, p, 4);
            p += __shfl_xor_sync(0xffffffffu, p, 2);
            p += __shfl_xor_sync(0xffffffffu, p, 1);
            if (ln8 == 0) {
                bool m;
                if (mask_int) m = ((const int*)mask)[b*Tt + t0] != 0;
                else          m = ((const unsigned char*)mask)[b*Tt + t0] != 0;
                s_s[t0] = m ? p * scale : -INFINITY;
            }
        }
    }
    __syncthreads();

    float lm = -INFINITY;
    for (int t = tid; t < Tt; t += 128) lm = fmaxf(lm, s_s[t]);
    #pragma unroll
    for (int off = 16; off; off >>= 1) lm = fmaxf(lm, __shfl_xor_sync(0xffffffffu, lm, off));
    if (lane == 0) red[warp] = lm;
    __syncthreads();
    const float mx = fmaxf(fmaxf(red[0], red[1]), fmaxf(red[2], red[3]));

    float ls = 0.0f;
    for (int t = tid; t < Tt; t += 128) {
        float e = __expf(s_s[t] - mx);
        s_s[t] = e;
        ls += e;
    }
    #pragma unroll
    for (int off = 16; off; off >>= 1) ls += __shfl_xor_sync(0xffffffffu, ls, off);
    __syncthreads();
    if (lane == 0) red[warp] = ls;
    __syncthreads();
    const float inv = 1.0f / (red[0] + red[1] + red[2] + red[3]);

    // u[d] = sum_t attn[t]*h[t,d]  (bf16x2 per lane: 64 values = 1 line per instr)
    float2 acc = make_float2(0.f, 0.f);
    for (int t = warp; t < Tt; t += 4) {
        const float w8 = s_s[t];
        const __nv_bfloat162 v = *(const __nv_bfloat162*)(h + ((size_t)(b*Tt + t))*MODEL + n*Dd + lane*2);
        const float2 f = __bfloat1622float2(v);
        acc.x = fmaf(w8, f.x, acc.x);
        acc.y = fmaf(w8, f.y, acc.y);
    }
    u_part[warp][lane*2]   = acc.x;
    u_part[warp][lane*2+1] = acc.y;
    __syncthreads();

    if (tid < 64) {
        qk_s[tid] = (u_part[0][tid] + u_part[1][tid] + u_part[2][tid] + u_part[3][tid]) * inv;
    }
    __syncthreads();
    if (tid < 64) {
        float c = 0.0f;
        const float* wvp = wv + (size_t)n*Dd*Dd + tid;
        #pragma unroll
        for (int dd = 0; dd < 64; dd++) c = fmaf(qk_s[dd], wvp[dd*Dd], c);
        out[((size_t)b*Nh + n)*Dd + tid] = c + q_s[tid];
    }
}

// ---------------- launch -------------------------------------------------------------
extern "C" void kernel_launch(void* const* d_in, const int* in_sizes, int n_in,
                              void* d_out, int out_size)
{
    const float* q    = (const float*)d_in[0];
    const float* seq  = (const float*)d_in[1];
    const float* rmsw = (const float*)d_in[2];
    const float* w1   = (const float*)d_in[3];
    const float* w2   = (const float*)d_in[4];
    const float* w3   = (const float*)d_in[5];
    const float* wk   = (const float*)d_in[6];
    const float* wv   = (const float*)d_in[7];
    const void*  msk  = d_in[8];
    float* out = (float*)d_out;

    __nv_bfloat16 *snb, *g, *hb, *w1b, *w2b, *w3b;
    cudaGetSymbolAddress((void**)&snb, d_snb);
    cudaGetSymbolAddress((void**)&g,   d_g);
    cudaGetSymbolAddress((void**)&hb,  d_hb);
    cudaGetSymbolAddress((void**)&w1b, d_w1b);
    cudaGetSymbolAddress((void**)&w2b, d_w2b);
    cudaGetSymbolAddress((void**)&w3b, d_w3b);

    const int SMEM = 98304;   // 96 KB per block, 2 blocks/SM
    cudaFuncSetAttribute(gemm_fused_kernel, cudaFuncAttributeMaxDynamicSharedMemorySize, SMEM);
    cudaFuncSetAttribute(gemm_out_kernel,   cudaFuncAttributeMaxDynamicSharedMemorySize, SMEM);

    prep_kernel<<<3072 + ROWS/8, 256>>>(w1, w2, w3, seq, rmsw, w1b, w2b, w3b, snb);

    cudaLaunchAttribute at[1];
    at[0].id = cudaLaunchAttributeProgrammaticStreamSerialization;
    at[0].val.programmaticStreamSerializationAllowed = 1;

    // GEMM1 with PDL (overlaps prep tail)
    {
        cudaLaunchConfig_t cfg = {};
        cfg.gridDim = dim3(FFNH/64, ROWS/128);
        cfg.blockDim = dim3(256);
        cfg.dynamicSmemBytes = SMEM;
        cfg.stream = 0;
        cfg.attrs = at;
        cfg.numAttrs = 1;
        cudaLaunchKernelEx(&cfg, gemm_fused_kernel, (const __nv_bfloat16*)snb,
                           (const __nv_bfloat16*)w1b, (const __nv_bfloat16*)w2b, g);
    }

    // GEMM2 with PDL (overlaps GEMM1 tail/epilogue)
    {
        cudaLaunchConfig_t cfg = {};
        cfg.gridDim = dim3(MODEL/128, ROWS/128);
        cfg.blockDim = dim3(256);
        cfg.dynamicSmemBytes = SMEM;
        cfg.stream = 0;
        cfg.attrs = at;
        cfg.numAttrs = 1;
        cudaLaunchKernelEx(&cfg, gemm_out_kernel, (const __nv_bfloat16*)g,
                           (const __nv_bfloat16*)w3b, seq, hb);
    }

    // attn with PDL (mask/q/qk phase overlaps GEMM2 tail/epilogue)
    {
        cudaLaunchConfig_t cfg = {};
        cfg.gridDim = dim3(Nh, Bb);
        cfg.blockDim = dim3(128);
        cfg.dynamicSmemBytes = 0;
        cfg.stream = 0;
        cfg.attrs = at;
        cfg.numAttrs = 1;
        cudaLaunchKernelEx(&cfg, attn_kernel, q, (const __nv_bfloat16*)hb, wk, wv, msk, out);
    }
}

// round 15
// speedup vs baseline: 1.0151x; 1.0151x over previous
#include <cuda_runtime.h>
#include <cuda_bf16.h>
#include <math.h>
#include <stdint.h>

#define Bb 256
#define Tt 200
#define Nh 8
#define Dd 64
#define MODEL 512
#define FFNH 2048
#define ROWS (Bb*Tt)            // 51200
#define EPSV 1.1920929e-07f

// ---------------- scratch (static device globals) ------------------------------
__device__ __nv_bfloat16 d_snb[(size_t)ROWS * MODEL];   // rmsnorm output (bf16)
__device__ __nv_bfloat16 d_g [(size_t)ROWS * FFNH];     // gated FFN activation (bf16)
__device__ float         d_h [(size_t)ROWS * MODEL];    // FFN output + residual (fp32)
__device__ __nv_bfloat16 d_w1b[MODEL * FFNH];
__device__ __nv_bfloat16 d_w2b[MODEL * FFNH];
__device__ __nv_bfloat16 d_w3b[FFNH * MODEL];

// ---------------- PTX helpers ----------------------------------------------------
__device__ __forceinline__ uint32_t smem_u32(const void* p) {
    uint32_t a;
    asm("{ .reg .u64 t; cvta.to.shared.u64 t, %1; cvt.u32.u64 %0, t; }" : "=r"(a) : "l"(p));
    return a;
}
#define CP_ASYNC(dst, src) asm volatile("cp.async.cg.shared.global [%0], [%1], 16;" :: "r"(dst), "l"(src))
#define CP_COMMIT()        asm volatile("cp.async.commit_group;" ::: "memory")
#define CP_WAIT1()         asm volatile("cp.async.wait_group 1;" ::: "memory")

#define LDMX4(r, addr) asm volatile( \
    "ldmatrix.sync.aligned.m8n8.x4.shared.b16 {%0,%1,%2,%3}, [%4];" \
    : "=r"((r)[0]), "=r"((r)[1]), "=r"((r)[2]), "=r"((r)[3]) : "r"(addr))
#define LDMX4T(r, addr) asm volatile( \
    "ldmatrix.sync.aligned.m8n8.x4.trans.shared.b16 {%0,%1,%2,%3}, [%4];" \
    : "=r"((r)[0]), "=r"((r)[1]), "=r"((r)[2]), "=r"((r)[3]) : "r"(addr))

__device__ __forceinline__ void mma_bf16(float* c, const uint32_t* a, const uint32_t* b) {
    asm volatile(
        "mma.sync.aligned.m16n8k16.row.col.f32.bf16.bf16.f32 "
        "{%0,%1,%2,%3}, {%4,%5,%6,%7}, {%8,%9}, {%0,%1,%2,%3};"
        : "+f"(c[0]), "+f"(c[1]), "+f"(c[2]), "+f"(c[3])
        : "r"(a[0]), "r"(a[1]), "r"(a[2]), "r"(a[3]), "r"(b[0]), "r"(b[1]));
}

// ================================================================================
// prep: pack w1/w2/w3 fp32->bf16  +  rmsnorm(seq)->bf16, ONE launch
// ================================================================================
__global__ __launch_bounds__(256) void prep_kernel(
    const float* __restrict__ w1, const float* __restrict__ w2,
    const float* __restrict__ w3, const float* __restrict__ seq,
    const float* __restrict__ rmsw,
    __nv_bfloat16* __restrict__ w1b, __nv_bfloat16* __restrict__ w2b,
    __nv_bfloat16* __restrict__ w3b, __nv_bfloat16* __restrict__ snb)
{
    const int bx = blockIdx.x;
    if (bx < 3072) {
        const int wsel = bx >> 10;          // 0,1,2
        const int i = (bx & 1023) * 256 + threadIdx.x;   // float4 index
        const float* src = (wsel == 0) ? w1 : (wsel == 1) ? w2 : w3;
        __nv_bfloat16* dst = (wsel == 0) ? w1b : (wsel == 1) ? w2b : w3b;
        const float4 v = ((const float4*)src)[i];
        __nv_bfloat162 lo = __floats2bfloat162_rn(v.x, v.y);
        __nv_bfloat162 hi = __floats2bfloat162_rn(v.z, v.w);
        uint2 st;
        st.x = *(uint32_t*)&lo;
        st.y = *(uint32_t*)&hi;
        ((uint2*)dst)[i] = st;
    } else {
        const int lane = threadIdx.x & 31;
        const int row = (bx - 3072) * 8 + (threadIdx.x >> 5);
        const float4* x = (const float4*)(seq + (size_t)row * MODEL);
        float4 xv[4];
        float s = 0.f;
        #pragma unroll
        for (int i = 0; i < 4; i++) {
            xv[i] = x[lane + 32*i];
            s += xv[i].x*xv[i].x + xv[i].y*xv[i].y + xv[i].z*xv[i].z + xv[i].w*xv[i].w;
        }
        #pragma unroll
        for (int off = 16; off; off >>= 1) s += __shfl_xor_sync(0xffffffffu, s, off);
        const float inv = rsqrtf(s * (1.0f / MODEL) + EPSV);
        const float4* wp = (const float4*)rmsw;
        #pragma unroll
        for (int i = 0; i < 4; i++) {
            const float4 wv = wp[lane + 32*i];
            __nv_bfloat162 o0 = __floats2bfloat162_rn(xv[i].x*inv*wv.x, xv[i].y*inv*wv.y);
            __nv_bfloat162 o1 = __floats2bfloat162_rn(xv[i].z*inv*wv.z, xv[i].w*inv*wv.w);
            uint2 st;
            st.x = *(uint32_t*)&o0;
            st.y = *(uint32_t*)&o1;
            ((uint2*)(snb + (size_t)row * MODEL))[lane + 32*i] = st;
        }
    }
}

// ================================================================================
// GEMM1: G = bf16( silu(A@W1) * (A@W2) )  — PDL consumer of prep
// block 128m x 64n(x2), k-step 64, 3-stage cp.async; 8 warps 2m x 4n
// ================================================================================
__global__ void __launch_bounds__(256, 2) gemm_fused_kernel(
    const __nv_bfloat16* __restrict__ A, const __nv_bfloat16* __restrict__ W1,
    const __nv_bfloat16* __restrict__ W2, __nv_bfloat16* __restrict__ G)
{
    extern __shared__ char sm[];
    const uint32_t sb = smem_u32(sm);
    const int tid = threadIdx.x;
    const int wid = tid >> 5, lane = tid & 31;
    const int wm = (wid >> 2) * 64, wn = (wid & 3) * 16;
    const int m0 = blockIdx.y * 128, n0 = blockIdx.x * 64;

    float accX[4][2][4], accG[4][2][4];
    #pragma unroll
    for (int i = 0; i < 4; i++)
        #pragma unroll
        for (int j = 0; j < 2; j++)
            #pragma unroll
            for (int v = 0; v < 4; v++) { accX[i][j][v] = 0.f; accG[i][j][v] = 0.f; }

    auto issue = [&](int st, int k0) {
        const uint32_t sA  = sb + (uint32_t)st*16384u;
        const uint32_t sB1 = sb + 49152u + (uint32_t)st*8192u;
        const uint32_t sB2 = sb + 73728u + (uint32_t)st*8192u;
        const int arow = tid >> 1;
        const __nv_bfloat16* ag = A + (size_t)(m0 + arow)*MODEL + k0 + (tid & 1)*32;
        const uint32_t abase = sA + (uint32_t)arow*128u;
        #pragma unroll
        for (int j = 0; j < 4; j++) {
            const int c = (tid & 1)*4 + j;
            CP_ASYNC(abase + (uint32_t)((c ^ (arow & 7)) << 4), ag + j*8);
        }
        const int brow = tid >> 2;
        const __nv_bfloat16* b1g = W1 + (size_t)(k0 + brow)*FFNH + n0 + (tid & 3)*16;
        const __nv_bfloat16* b2g = W2 + (size_t)(k0 + brow)*FFNH + n0 + (tid & 3)*16;
        const uint32_t b1base = sB1 + (uint32_t)brow*128u;
        const uint32_t b2base = sB2 + (uint32_t)brow*128u;
        #pragma unroll
        for (int j = 0; j < 2; j++) {
            const int c = (tid & 3)*2 + j;
            const uint32_t sw = (uint32_t)((c ^ (brow & 7)) << 4);
            CP_ASYNC(b1base + sw, b1g + j*8);
            CP_ASYNC(b2base + sw, b2g + j*8);
        }
        CP_COMMIT();
    };

    // wait for prep (snb / w1b / w2b ready); setup above is h-independent
    cudaGridDependencySynchronize();

    const int NT = MODEL / 64;  // 8
    issue(0, 0);
    issue(1, 64);

    auto step = [&](int kt, int cur, int nxt) {
        CP_WAIT1();
        __syncthreads();
        if (kt + 2 < NT) issue(nxt, (kt + 2)*64); else CP_COMMIT();

        const uint32_t sA  = sb + (uint32_t)cur*16384u;
        const uint32_t sB1 = sb + 49152u + (uint32_t)cur*8192u;
        const uint32_t sB2 = sb + 73728u + (uint32_t)cur*8192u;

        #pragma unroll
        for (int k16 = 0; k16 < 4; ++k16) {
            uint32_t af[4][4];
            #pragma unroll
            for (int mt = 0; mt < 4; mt++) {
                const int row = wm + mt*16 + (lane & 15);
                const uint32_t a = sA + (uint32_t)row*128u
                    + (uint32_t)((((k16*2 + (lane >> 4)) ^ (row & 7))) << 4);
                LDMX4(af[mt], a);
            }
            uint32_t b1[4], b2[4];
            {
                const int krow = k16*16 + (lane & 15);
                const int nch = (wid & 3)*2 + (lane >> 4);
                const uint32_t off = (uint32_t)krow*128u + (uint32_t)((nch ^ (lane & 7)) << 4);
                LDMX4T(b1, sB1 + off);
                LDMX4T(b2, sB2 + off);
            }
            #pragma unroll
            for (int mt = 0; mt < 4; mt++)
                #pragma unroll
                for (int nt = 0; nt < 2; nt++) {
                    mma_bf16(accX[mt][nt], af[mt], &b1[nt*2]);
                    mma_bf16(accG[mt][nt], af[mt], &b2[nt*2]);
                }
        }
    };

    for (int kt0 = 0; kt0 < NT; kt0 += 3) {
        step(kt0, 0, 2);
        if (kt0 + 1 < NT) step(kt0 + 1, 1, 0);
        if (kt0 + 2 < NT) step(kt0 + 2, 2, 1);
    }

    // allow gemm2 blocks to launch while we run the epilogue
    cudaTriggerProgrammaticLaunchCompletion();

    // epilogue: silu(X)*G -> bf16x2
    const int r = lane >> 2, q = lane & 3;
    #pragma unroll
    for (int mt = 0; mt < 4; mt++) {
        #pragma unroll
        for (int nt = 0; nt < 2; nt++) {
            const int col = n0 + wn + nt*8 + 2*q;
            #pragma unroll
            for (int half = 0; half < 2; half++) {
                const int row = m0 + wm + mt*16 + r + half*8;
                const float x0 = accX[mt][nt][half*2 + 0], g0 = accG[mt][nt][half*2 + 0];
                const float x1 = accX[mt][nt][half*2 + 1], g1 = accG[mt][nt][half*2 + 1];
                const float o0 = x0 / (1.f + __expf(-x0)) * g0;
                const float o1 = x1 / (1.f + __expf(-x1)) * g1;
                __nv_bfloat162 st = __floats2bfloat162_rn(o0, o1);
                *(__nv_bfloat162*)(G + (size_t)row*FFNH + col) = st;
            }
        }
    }
}

// ================================================================================
// GEMM2: H = A@W3 + seq  (fp32 out) — 128x128 tile, PDL consumer of GEMM1
// ================================================================================
__global__ void __launch_bounds__(256, 2) gemm_out_kernel(
    const __nv_bfloat16* __restrict__ A, const __nv_bfloat16* __restrict__ W3,
    const float* __restrict__ seq, float* __restrict__ H)
{
    extern __shared__ char sm[];
    const uint32_t sb = smem_u32(sm);
    const int tid = threadIdx.x;
    const int wid = tid >> 5, lane = tid & 31;
    const int wm = (wid >> 2) * 64, wn = (wid & 3) * 32;
    const int m0 = blockIdx.y * 128, n0 = blockIdx.x * 128;

    float acc[4][4][4];
    #pragma unroll
    for (int i = 0; i < 4; i++)
        #pragma unroll
        for (int j = 0; j < 4; j++)
            #pragma unroll
            for (int v = 0; v < 4; v++) acc[i][j][v] = 0.f;

    auto issue = [&](int st, int k0) {
        const uint32_t sA = sb + (uint32_t)st*16384u;
        const uint32_t sB = sb + 49152u + (uint32_t)st*16384u;
        const int arow = tid >> 1;
        const __nv_bfloat16* ag = A + (size_t)(m0 + arow)*FFNH + k0 + (tid & 1)*32;
        const uint32_t abase = sA + (uint32_t)arow*128u;
        #pragma unroll
        for (int j = 0; j < 4; j++) {
            const int c = (tid & 1)*4 + j;
            CP_ASYNC(abase + (uint32_t)((c ^ (arow & 7)) << 4), ag + j*8);
        }
        const int brow = tid >> 2;
        const __nv_bfloat16* bg = W3 + (size_t)(k0 + brow)*MODEL + n0 + (tid & 3)*32;
        const uint32_t bbase = sB + (uint32_t)brow*256u;
        #pragma unroll
        for (int j = 0; j < 4; j++) {
            const int c = (tid & 3)*4 + j;
            CP_ASYNC(bbase + (uint32_t)((c ^ (brow & 7)) << 4), bg + j*8);
        }
        CP_COMMIT();
    };

    // wait for GEMM1 completion (A = g); setup above ran concurrently
    cudaGridDependencySynchronize();

    const int NT = FFNH / 64;  // 32
    issue(0, 0);
    issue(1, 64);

    auto step = [&](int kt, int cur, int nxt) {
        CP_WAIT1();
        __syncthreads();
        if (kt + 2 < NT) issue(nxt, (kt + 2)*64); else CP_COMMIT();

        const uint32_t sA = sb + (uint32_t)cur*16384u;
        const uint32_t sB = sb + 49152u + (uint32_t)cur*16384u;

        #pragma unroll
        for (int k16 = 0; k16 < 4; ++k16) {
            uint32_t af[4][4];
            #pragma unroll
            for (int mt = 0; mt < 4; mt++) {
                const int row = wm + mt*16 + (lane & 15);
                const uint32_t a = sA + (uint32_t)row*128u
                    + (uint32_t)((((k16*2 + (lane >> 4)) ^ (row & 7))) << 4);
                LDMX4(af[mt], a);
            }
            uint32_t bf[8];
            {
                const int krow = k16*16 + (lane & 15);
                const uint32_t rowoff = (uint32_t)krow*256u;
                #pragma unroll
                for (int hh = 0; hh < 2; hh++) {
                    const int nch = (wid & 3)*4 + hh*2 + (lane >> 4);
                    LDMX4T(&bf[hh*4], sB + rowoff + (uint32_t)((nch ^ (lane & 7)) << 4));
                }
            }
            #pragma unroll
            for (int mt = 0; mt < 4; mt++)
                #pragma unroll
                for (int nt = 0; nt < 4; nt++)
                    mma_bf16(acc[mt][nt], af[mt], &bf[nt*2]);
        }
    };

    for (int kt0 = 0; kt0 < NT; kt0 += 3) {
        step(kt0, 0, 2);
        if (kt0 + 1 < NT) step(kt0 + 1, 1, 0);
        if (kt0 + 2 < NT) step(kt0 + 2, 2, 1);
    }

    // allow attn blocks to launch while we run the epilogue
    cudaTriggerProgrammaticLaunchCompletion();

    // epilogue: + seq residual
    const int r = lane >> 2, q = lane & 3;
    #pragma unroll
    for (int mt = 0; mt < 4; mt++) {
        #pragma unroll
        for (int nt = 0; nt < 4; nt++) {
            const int col = n0 + wn + nt*8 + 2*q;
            #pragma unroll
            for (int half = 0; half < 2; half++) {
                const int row = m0 + wm + mt*16 + r + half*8;
                const float2 s = *(const float2*)(seq + (size_t)row*MODEL + col);
                float2 o;
                o.x = acc[mt][nt][half*2 + 0] + s.x;
                o.y = acc[mt][nt][half*2 + 1] + s.y;
                *(float2*)(H + (size_t)row*MODEL + col) = o;
            }
        }
    }
}

// ================================================================================
// fused single-query attention — coalesced score phase (16 lanes per row), fp32 h
// ================================================================================
__global__ __launch_bounds__(128) void attn_kernel(
    const float* __restrict__ q, const float* __restrict__ h,
    const float* __restrict__ wk, const float* __restrict__ wv,
    const void* __restrict__ mask, float* __restrict__ out)
{
    const int n = blockIdx.x;
    const int b = blockIdx.y;
    const int tid = threadIdx.x;
    const int lane = tid & 31, warp = tid >> 5;

    __shared__ float q_s[64], qk_s[64], s_s[Tt], u_part[4][64], red[4];
    __shared__ int mz[4];

    // ---- pre-sync work: independent of h (mask, q, w_k @ q) ----
    int nz = 0;
    if (tid < 64) {
        const unsigned char* mb = (const unsigned char*)mask;
        nz = mb[4*tid + 1] | mb[4*tid + 2] | mb[4*tid + 3];
    }
    const int wany = __any_sync(0xffffffffu, nz != 0) ? 1 : 0;
    if (lane == 0) mz[warp] = wany;

    if (tid < 64) q_s[tid] = q[((size_t)b*Nh + n)*Dd + tid];
    __syncthreads();

    const int mask_int = !(mz[0] | mz[1]);

    if (tid < 64) {
        const float4* wkp = (const float4*)(wk + ((size_t)n*Dd + tid)*Dd);
        float a0 = 0.f, a1 = 0.f;
        #pragma unroll 8
        for (int e = 0; e < 16; e++) {
            const float4 v = wkp[e];
            a0 = fmaf(v.x, q_s[4*e+0], a0);
            a1 = fmaf(v.y, q_s[4*e+1], a1);
            a0 = fmaf(v.z, q_s[4*e+2], a0);
            a1 = fmaf(v.w, q_s[4*e+3], a1);
        }
        qk_s[tid] = a0 + a1;
    }
    __syncthreads();

    // ---- wait for GEMM2 (h ready) ----
    cudaGridDependencySynchronize();

    const float scale = 0.125f;

    // scores: 16 lanes per row — coalesced LDG.128 (4 wavefronts/instr vs 32)
    {
        const int sub  = lane >> 4;    // row within warp pair
        const int ln16 = lane & 15;
        const float4 qv = *(const float4*)(qk_s + ln16*4);   // hoisted, reused
        #pragma unroll 5
        for (int t0 = warp*2 + sub; t0 < Tt; t0 += 8) {
            const float4 v = *(const float4*)(h + ((size_t)(b*Tt + t0))*MODEL + n*Dd + ln16*4);
            float p = v.x*qv.x + v.y*qv.y + v.z*qv.z + v.w*qv.w;
            p += __shfl_xor_sync(0xffffffffu, p, 8);
            p += __shfl_xor_sync(0xffffffffu, p, 4);
            p += __shfl_xor_sync(0xffffffffu, p, 2);
            p += __shfl_xor_sync(0xffffffffu, p, 1);
            if (ln16 == 0) {
                bool m;
                if (mask_int) m = ((const int*)mask)[b*Tt + t0] != 0;
                else          m = ((const unsigned char*)mask)[b*Tt + t0] != 0;
                s_s[t0] = m ? p * scale : -INFINITY;
            }
        }
    }
    __syncthreads();

    float lm = -INFINITY;
    for (int t = tid; t < Tt; t += 128) lm = fmaxf(lm, s_s[t]);
    #pragma unroll
    for (int off = 16; off; off >>= 1) lm = fmaxf(lm, __shfl_xor_sync(0xffffffffu, lm, off));
    if (lane == 0) red[warp] = lm;
    __syncthreads();
    const float mx = fmaxf(fmaxf(red[0], red[1]), fmaxf(red[2], red[3]));

    float ls = 0.0f;
    for (int t = tid; t < Tt; t += 128) {
        float e = __expf(s_s[t] - mx);
        s_s[t] = e;
        ls += e;
    }
    #pragma unroll
    for (int off = 16; off; off >>= 1) ls += __shfl_xor_sync(0xffffffffu, ls, off);
    __syncthreads();
    if (lane == 0) red[warp] = ls;
    __syncthreads();
    const float inv = 1.0f / (red[0] + red[1] + red[2] + red[3]);

    const int d2 = (tid & 31), chunk = tid >> 5;
    float2 acc = make_float2(0.f, 0.f);
    for (int t = chunk; t < Tt; t += 4) {
        const float w8 = s_s[t];
        const float2 v = *(const float2*)(h + ((size_t)(b*Tt + t))*MODEL + n*Dd + d2*2);
        acc.x = fmaf(w8, v.x, acc.x);
        acc.y = fmaf(w8, v.y, acc.y);
    }
    u_part[chunk][d2*2]   = acc.x;
    u_part[chunk][d2*2+1] = acc.y;
    __syncthreads();

    if (tid < 64) {
        qk_s[tid] = (u_part[0][tid] + u_part[1][tid] + u_part[2][tid] + u_part[3][tid]) * inv;
    }
    __syncthreads();
    if (tid < 64) {
        float c = 0.0f;
        const float* wvp = wv + (size_t)n*Dd*Dd + tid;
        #pragma unroll
        for (int dd = 0; dd < 64; dd++) c = fmaf(qk_s[dd], wvp[dd*Dd], c);
        out[((size_t)b*Nh + n)*Dd + tid] = c + q_s[tid];
    }
}

// ---------------- launch -------------------------------------------------------------
extern "C" void kernel_launch(void* const* d_in, const int* in_sizes, int n_in,
                              void* d_out, int out_size)
{
    const float* q    = (const float*)d_in[0];
    const float* seq  = (const float*)d_in[1];
    const float* rmsw = (const float*)d_in[2];
    const float* w1   = (const float*)d_in[3];
    const float* w2   = (const float*)d_in[4];
    const float* w3   = (const float*)d_in[5];
    const float* wk   = (const float*)d_in[6];
    const float* wv   = (const float*)d_in[7];
    const void*  msk  = d_in[8];
    float* out = (float*)d_out;

    __nv_bfloat16 *snb, *g, *w1b, *w2b, *w3b;
    float *h;
    cudaGetSymbolAddress((void**)&snb, d_snb);
    cudaGetSymbolAddress((void**)&g,   d_g);
    cudaGetSymbolAddress((void**)&h,   d_h);
    cudaGetSymbolAddress((void**)&w1b, d_w1b);
    cudaGetSymbolAddress((void**)&w2b, d_w2b);
    cudaGetSymbolAddress((void**)&w3b, d_w3b);

    const int SMEM = 98304;   // 96 KB per block, 2 blocks/SM
    cudaFuncSetAttribute(gemm_fused_kernel, cudaFuncAttributeMaxDynamicSharedMemorySize, SMEM);
    cudaFuncSetAttribute(gemm_out_kernel,   cudaFuncAttributeMaxDynamicSharedMemorySize, SMEM);

    prep_kernel<<<3072 + ROWS/8, 256>>>(w1, w2, w3, seq, rmsw, w1b, w2b, w3b, snb);

    cudaLaunchAttribute at[1];
    at[0].id = cudaLaunchAttributeProgrammaticStreamSerialization;
    at[0].val.programmaticStreamSerializationAllowed = 1;

    // GEMM1 with PDL (overlaps prep tail)
    {
        cudaLaunchConfig_t cfg = {};
        cfg.gridDim = dim3(FFNH/64, ROWS/128);
        cfg.blockDim = dim3(256);
        cfg.dynamicSmemBytes = SMEM;
        cfg.stream = 0;
        cfg.attrs = at;
        cfg.numAttrs = 1;
        cudaLaunchKernelEx(&cfg, gemm_fused_kernel, (const __nv_bfloat16*)snb,
                           (const __nv_bfloat16*)w1b, (const __nv_bfloat16*)w2b, g);
    }

    // GEMM2 with PDL (overlaps GEMM1 tail/epilogue)
    {
        cudaLaunchConfig_t cfg = {};
        cfg.gridDim = dim3(MODEL/128, ROWS/128);
        cfg.blockDim = dim3(256);
        cfg.dynamicSmemBytes = SMEM;
        cfg.stream = 0;
        cfg.attrs = at;
        cfg.numAttrs = 1;
        cudaLaunchKernelEx(&cfg, gemm_out_kernel, (const __nv_bfloat16*)g,
                           (const __nv_bfloat16*)w3b, seq, h);
    }

    // attn with PDL (mask/q/qk phase overlaps GEMM2 tail/epilogue)
    {
        cudaLaunchConfig_t cfg = {};
        cfg.gridDim = dim3(Nh, Bb);
        cfg.blockDim = dim3(128);
        cfg.dynamicSmemBytes = 0;
        cfg.stream = 0;
        cfg.attrs = at;
        cfg.numAttrs = 1;
        cudaLaunchKernelEx(&cfg, attn_kernel, q, (const float*)h, wk, wv, msk, out);
    }
}

// round 16
// speedup vs baseline: 1.0567x; 1.0411x over previous
#include <cuda_runtime.h>
#include <cuda_bf16.h>
#include <math.h>
#include <stdint.h>

#define Bb 256
#define Tt 200
#define Nh 8
#define Dd 64
#define MODEL 512
#define FFNH 2048
#define ROWS (Bb*Tt)            // 51200
#define EPSV 1.1920929e-07f

// ---------------- scratch (static device globals) ------------------------------
__device__ __nv_bfloat16 d_snb[(size_t)ROWS * MODEL];   // rmsnorm output (bf16)
__device__ __nv_bfloat16 d_g [(size_t)ROWS * FFNH];     // gated FFN activation (bf16)
__device__ float         d_h [(size_t)ROWS * MODEL];    // FFN output + residual (fp32)
__device__ __nv_bfloat16 d_w1b[MODEL * FFNH];
__device__ __nv_bfloat16 d_w2b[MODEL * FFNH];
__device__ __nv_bfloat16 d_w3b[FFNH * MODEL];

// ---------------- PTX helpers ----------------------------------------------------
__device__ __forceinline__ uint32_t smem_u32(const void* p) {
    uint32_t a;
    asm("{ .reg .u64 t; cvta.to.shared.u64 t, %1; cvt.u32.u64 %0, t; }" : "=r"(a) : "l"(p));
    return a;
}
#define CP_ASYNC(dst, src) asm volatile("cp.async.cg.shared.global [%0], [%1], 16;" :: "r"(dst), "l"(src))
#define CP_COMMIT()        asm volatile("cp.async.commit_group;" ::: "memory")
#define CP_WAIT1()         asm volatile("cp.async.wait_group 1;" ::: "memory")

#define LDMX4(r, addr) asm volatile( \
    "ldmatrix.sync.aligned.m8n8.x4.shared.b16 {%0,%1,%2,%3}, [%4];" \
    : "=r"((r)[0]), "=r"((r)[1]), "=r"((r)[2]), "=r"((r)[3]) : "r"(addr))
#define LDMX4T(r, addr) asm volatile( \
    "ldmatrix.sync.aligned.m8n8.x4.trans.shared.b16 {%0,%1,%2,%3}, [%4];" \
    : "=r"((r)[0]), "=r"((r)[1]), "=r"((r)[2]), "=r"((r)[3]) : "r"(addr))

__device__ __forceinline__ void mma_bf16(float* c, const uint32_t* a, const uint32_t* b) {
    asm volatile(
        "mma.sync.aligned.m16n8k16.row.col.f32.bf16.bf16.f32 "
        "{%0,%1,%2,%3}, {%4,%5,%6,%7}, {%8,%9}, {%0,%1,%2,%3};"
        : "+f"(c[0]), "+f"(c[1]), "+f"(c[2]), "+f"(c[3])
        : "r"(a[0]), "r"(a[1]), "r"(a[2]), "r"(a[3]), "r"(b[0]), "r"(b[1]));
}

// fast silu: x * sigmoid(x) via MUFU.RCP (rel err ~2^-21, invisible under bf16 store)
__device__ __forceinline__ float fast_silu(float x) {
    return __fdividef(x, 1.0f + __expf(-x));
}

// ================================================================================
// prep: pack w1/w2/w3 fp32->bf16  +  rmsnorm(seq)->bf16, ONE launch
// ================================================================================
__global__ __launch_bounds__(256) void prep_kernel(
    const float* __restrict__ w1, const float* __restrict__ w2,
    const float* __restrict__ w3, const float* __restrict__ seq,
    const float* __restrict__ rmsw,
    __nv_bfloat16* __restrict__ w1b, __nv_bfloat16* __restrict__ w2b,
    __nv_bfloat16* __restrict__ w3b, __nv_bfloat16* __restrict__ snb)
{
    const int bx = blockIdx.x;
    if (bx < 3072) {
        const int wsel = bx >> 10;          // 0,1,2
        const int i = (bx & 1023) * 256 + threadIdx.x;   // float4 index
        const float* src = (wsel == 0) ? w1 : (wsel == 1) ? w2 : w3;
        __nv_bfloat16* dst = (wsel == 0) ? w1b : (wsel == 1) ? w2b : w3b;
        const float4 v = ((const float4*)src)[i];
        __nv_bfloat162 lo = __floats2bfloat162_rn(v.x, v.y);
        __nv_bfloat162 hi = __floats2bfloat162_rn(v.z, v.w);
        uint2 st;
        st.x = *(uint32_t*)&lo;
        st.y = *(uint32_t*)&hi;
        ((uint2*)dst)[i] = st;
    } else {
        const int lane = threadIdx.x & 31;
        const int row = (bx - 3072) * 8 + (threadIdx.x >> 5);
        const float4* x = (const float4*)(seq + (size_t)row * MODEL);
        float4 xv[4];
        float s = 0.f;
        #pragma unroll
        for (int i = 0; i < 4; i++) {
            xv[i] = x[lane + 32*i];
            s += xv[i].x*xv[i].x + xv[i].y*xv[i].y + xv[i].z*xv[i].z + xv[i].w*xv[i].w;
        }
        #pragma unroll
        for (int off = 16; off; off >>= 1) s += __shfl_xor_sync(0xffffffffu, s, off);
        const float inv = rsqrtf(s * (1.0f / MODEL) + EPSV);
        const float4* wp = (const float4*)rmsw;
        #pragma unroll
        for (int i = 0; i < 4; i++) {
            const float4 wv = wp[lane + 32*i];
            __nv_bfloat162 o0 = __floats2bfloat162_rn(xv[i].x*inv*wv.x, xv[i].y*inv*wv.y);
            __nv_bfloat162 o1 = __floats2bfloat162_rn(xv[i].z*inv*wv.z, xv[i].w*inv*wv.w);
            uint2 st;
            st.x = *(uint32_t*)&o0;
            st.y = *(uint32_t*)&o1;
            ((uint2*)(snb + (size_t)row * MODEL))[lane + 32*i] = st;
        }
    }
}

// ================================================================================
// GEMM1: G = bf16( silu(A@W1) * (A@W2) )  — PDL consumer of prep
// block 128m x 64n(x2), k-step 64, 3-stage cp.async; 8 warps 2m x 4n
// ================================================================================
__global__ void __launch_bounds__(256, 2) gemm_fused_kernel(
    const __nv_bfloat16* __restrict__ A, const __nv_bfloat16* __restrict__ W1,
    const __nv_bfloat16* __restrict__ W2, __nv_bfloat16* __restrict__ G)
{
    extern __shared__ char sm[];
    const uint32_t sb = smem_u32(sm);
    const int tid = threadIdx.x;
    const int wid = tid >> 5, lane = tid & 31;
    const int wm = (wid >> 2) * 64, wn = (wid & 3) * 16;
    const int m0 = blockIdx.y * 128, n0 = blockIdx.x * 64;

    float accX[4][2][4], accG[4][2][4];
    #pragma unroll
    for (int i = 0; i < 4; i++)
        #pragma unroll
        for (int j = 0; j < 2; j++)
            #pragma unroll
            for (int v = 0; v < 4; v++) { accX[i][j][v] = 0.f; accG[i][j][v] = 0.f; }

    auto issue = [&](int st, int k0) {
        const uint32_t sA  = sb + (uint32_t)st*16384u;
        const uint32_t sB1 = sb + 49152u + (uint32_t)st*8192u;
        const uint32_t sB2 = sb + 73728u + (uint32_t)st*8192u;
        const int arow = tid >> 1;
        const __nv_bfloat16* ag = A + (size_t)(m0 + arow)*MODEL + k0 + (tid & 1)*32;
        const uint32_t abase = sA + (uint32_t)arow*128u;
        #pragma unroll
        for (int j = 0; j < 4; j++) {
            const int c = (tid & 1)*4 + j;
            CP_ASYNC(abase + (uint32_t)((c ^ (arow & 7)) << 4), ag + j*8);
        }
        const int brow = tid >> 2;
        const __nv_bfloat16* b1g = W1 + (size_t)(k0 + brow)*FFNH + n0 + (tid & 3)*16;
        const __nv_bfloat16* b2g = W2 + (size_t)(k0 + brow)*FFNH + n0 + (tid & 3)*16;
        const uint32_t b1base = sB1 + (uint32_t)brow*128u;
        const uint32_t b2base = sB2 + (uint32_t)brow*128u;
        #pragma unroll
        for (int j = 0; j < 2; j++) {
            const int c = (tid & 3)*2 + j;
            const uint32_t sw = (uint32_t)((c ^ (brow & 7)) << 4);
            CP_ASYNC(b1base + sw, b1g + j*8);
            CP_ASYNC(b2base + sw, b2g + j*8);
        }
        CP_COMMIT();
    };

    // wait for prep (snb / w1b / w2b ready); setup above is input-independent
    cudaGridDependencySynchronize();

    const int NT = MODEL / 64;  // 8
    issue(0, 0);
    issue(1, 64);

    auto step = [&](int kt, int cur, int nxt) {
        CP_WAIT1();
        __syncthreads();
        if (kt + 2 < NT) issue(nxt, (kt + 2)*64); else CP_COMMIT();

        const uint32_t sA  = sb + (uint32_t)cur*16384u;
        const uint32_t sB1 = sb + 49152u + (uint32_t)cur*8192u;
        const uint32_t sB2 = sb + 73728u + (uint32_t)cur*8192u;

        #pragma unroll
        for (int k16 = 0; k16 < 4; ++k16) {
            uint32_t af[4][4];
            #pragma unroll
            for (int mt = 0; mt < 4; mt++) {
                const int row = wm + mt*16 + (lane & 15);
                const uint32_t a = sA + (uint32_t)row*128u
                    + (uint32_t)((((k16*2 + (lane >> 4)) ^ (row & 7))) << 4);
                LDMX4(af[mt], a);
            }
            uint32_t b1[4], b2[4];
            {
                const int krow = k16*16 + (lane & 15);
                const int nch = (wid & 3)*2 + (lane >> 4);
                const uint32_t off = (uint32_t)krow*128u + (uint32_t)((nch ^ (lane & 7)) << 4);
                LDMX4T(b1, sB1 + off);
                LDMX4T(b2, sB2 + off);
            }
            #pragma unroll
            for (int mt = 0; mt < 4; mt++)
                #pragma unroll
                for (int nt = 0; nt < 2; nt++) {
                    mma_bf16(accX[mt][nt], af[mt], &b1[nt*2]);
                    mma_bf16(accG[mt][nt], af[mt], &b2[nt*2]);
                }
        }
    };

    for (int kt0 = 0; kt0 < NT; kt0 += 3) {
        step(kt0, 0, 2);
        if (kt0 + 1 < NT) step(kt0 + 1, 1, 0);
        if (kt0 + 2 < NT) step(kt0 + 2, 2, 1);
    }

    // allow gemm2 blocks to launch while we run the epilogue
    cudaTriggerProgrammaticLaunchCompletion();

    // epilogue: silu(X)*G -> bf16x2  (fast-div silu; no precise-div sequence)
    const int r = lane >> 2, q = lane & 3;
    #pragma unroll
    for (int mt = 0; mt < 4; mt++) {
        #pragma unroll
        for (int nt = 0; nt < 2; nt++) {
            const int col = n0 + wn + nt*8 + 2*q;
            #pragma unroll
            for (int half = 0; half < 2; half++) {
                const int row = m0 + wm + mt*16 + r + half*8;
                const float x0 = accX[mt][nt][half*2 + 0], g0 = accG[mt][nt][half*2 + 0];
                const float x1 = accX[mt][nt][half*2 + 1], g1 = accG[mt][nt][half*2 + 1];
                const float o0 = fast_silu(x0) * g0;
                const float o1 = fast_silu(x1) * g1;
                __nv_bfloat162 st = __floats2bfloat162_rn(o0, o1);
                *(__nv_bfloat162*)(G + (size_t)row*FFNH + col) = st;
            }
        }
    }
}

// ================================================================================
// GEMM2: H = A@W3 + seq  (fp32 out) — 128x128 tile, PDL consumer of GEMM1
// ================================================================================
__global__ void __launch_bounds__(256, 2) gemm_out_kernel(
    const __nv_bfloat16* __restrict__ A, const __nv_bfloat16* __restrict__ W3,
    const float* __restrict__ seq, float* __restrict__ H)
{
    extern __shared__ char sm[];
    const uint32_t sb = smem_u32(sm);
    const int tid = threadIdx.x;
    const int wid = tid >> 5, lane = tid & 31;
    const int wm = (wid >> 2) * 64, wn = (wid & 3) * 32;
    const int m0 = blockIdx.y * 128, n0 = blockIdx.x * 128;

    float acc[4][4][4];
    #pragma unroll
    for (int i = 0; i < 4; i++)
        #pragma unroll
        for (int j = 0; j < 4; j++)
            #pragma unroll
            for (int v = 0; v < 4; v++) acc[i][j][v] = 0.f;

    auto issue = [&](int st, int k0) {
        const uint32_t sA = sb + (uint32_t)st*16384u;
        const uint32_t sB = sb + 49152u + (uint32_t)st*16384u;
        const int arow = tid >> 1;
        const __nv_bfloat16* ag = A + (size_t)(m0 + arow)*FFNH + k0 + (tid & 1)*32;
        const uint32_t abase = sA + (uint32_t)arow*128u;
        #pragma unroll
        for (int j = 0; j < 4; j++) {
            const int c = (tid & 1)*4 + j;
            CP_ASYNC(abase + (uint32_t)((c ^ (arow & 7)) << 4), ag + j*8);
        }
        const int brow = tid >> 2;
        const __nv_bfloat16* bg = W3 + (size_t)(k0 + brow)*MODEL + n0 + (tid & 3)*32;
        const uint32_t bbase = sB + (uint32_t)brow*256u;
        #pragma unroll
        for (int j = 0; j < 4; j++) {
            const int c = (tid & 3)*4 + j;
            CP_ASYNC(bbase + (uint32_t)((c ^ (brow & 7)) << 4), bg + j*8);
        }
        CP_COMMIT();
    };

    // wait for GEMM1 completion (A = g); setup above ran concurrently
    cudaGridDependencySynchronize();

    const int NT = FFNH / 64;  // 32
    issue(0, 0);
    issue(1, 64);

    auto step = [&](int kt, int cur, int nxt) {
        CP_WAIT1();
        __syncthreads();
        if (kt + 2 < NT) issue(nxt, (kt + 2)*64); else CP_COMMIT();

        const uint32_t sA = sb + (uint32_t)cur*16384u;
        const uint32_t sB = sb + 49152u + (uint32_t)cur*16384u;

        #pragma unroll
        for (int k16 = 0; k16 < 4; ++k16) {
            uint32_t af[4][4];
            #pragma unroll
            for (int mt = 0; mt < 4; mt++) {
                const int row = wm + mt*16 + (lane & 15);
                const uint32_t a = sA + (uint32_t)row*128u
                    + (uint32_t)((((k16*2 + (lane >> 4)) ^ (row & 7))) << 4);
                LDMX4(af[mt], a);
            }
            uint32_t bf[8];
            {
                const int krow = k16*16 + (lane & 15);
                const uint32_t rowoff = (uint32_t)krow*256u;
                #pragma unroll
                for (int hh = 0; hh < 2; hh++) {
                    const int nch = (wid & 3)*4 + hh*2 + (lane >> 4);
                    LDMX4T(&bf[hh*4], sB + rowoff + (uint32_t)((nch ^ (lane & 7)) << 4));
                }
            }
            #pragma unroll
            for (int mt = 0; mt < 4; mt++)
                #pragma unroll
                for (int nt = 0; nt < 4; nt++)
                    mma_bf16(acc[mt][nt], af[mt], &bf[nt*2]);
        }
    };

    for (int kt0 = 0; kt0 < NT; kt0 += 3) {
        step(kt0, 0, 2);
        if (kt0 + 1 < NT) step(kt0 + 1, 1, 0);
        if (kt0 + 2 < NT) step(kt0 + 2, 2, 1);
    }

    // allow attn blocks to launch while we run the epilogue
    cudaTriggerProgrammaticLaunchCompletion();

    // epilogue: + seq residual
    const int r = lane >> 2, q = lane & 3;
    #pragma unroll
    for (int mt = 0; mt < 4; mt++) {
        #pragma unroll
        for (int nt = 0; nt < 4; nt++) {
            const int col = n0 + wn + nt*8 + 2*q;
            #pragma unroll
            for (int half = 0; half < 2; half++) {
                const int row = m0 + wm + mt*16 + r + half*8;
                const float2 s = *(const float2*)(seq + (size_t)row*MODEL + col);
                float2 o;
                o.x = acc[mt][nt][half*2 + 0] + s.x;
                o.y = acc[mt][nt][half*2 + 1] + s.y;
                *(float2*)(H + (size_t)row*MODEL + col) = o;
            }
        }
    }
}

// ================================================================================
// fused single-query attention — coalesced score phase (16 lanes per row), fp32 h
// ================================================================================
__global__ __launch_bounds__(128) void attn_kernel(
    const float* __restrict__ q, const float* __restrict__ h,
    const float* __restrict__ wk, const float* __restrict__ wv,
    const void* __restrict__ mask, float* __restrict__ out)
{
    const int n = blockIdx.x;
    const int b = blockIdx.y;
    const int tid = threadIdx.x;
    const int lane = tid & 31, warp = tid >> 5;

    __shared__ float q_s[64], qk_s[64], s_s[Tt], u_part[4][64], red[4];
    __shared__ int mz[4];

    // ---- pre-sync work: independent of h (mask, q, w_k @ q) ----
    int nz = 0;
    if (tid < 64) {
        const unsigned char* mb = (const unsigned char*)mask;
        nz = mb[4*tid + 1] | mb[4*tid + 2] | mb[4*tid + 3];
    }
    const int wany = __any_sync(0xffffffffu, nz != 0) ? 1 : 0;
    if (lane == 0) mz[warp] = wany;

    if (tid < 64) q_s[tid] = q[((size_t)b*Nh + n)*Dd + tid];
    __syncthreads();

    const int mask_int = !(mz[0] | mz[1]);

    if (tid < 64) {
        const float4* wkp = (const float4*)(wk + ((size_t)n*Dd + tid)*Dd);
        float a0 = 0.f, a1 = 0.f;
        #pragma unroll 8
        for (int e = 0; e < 16; e++) {
            const float4 v = wkp[e];
            a0 = fmaf(v.x, q_s[4*e+0], a0);
            a1 = fmaf(v.y, q_s[4*e+1], a1);
            a0 = fmaf(v.z, q_s[4*e+2], a0);
            a1 = fmaf(v.w, q_s[4*e+3], a1);
        }
        qk_s[tid] = a0 + a1;
    }
    __syncthreads();

    // ---- wait for GEMM2 (h ready) ----
    cudaGridDependencySynchronize();

    const float scale = 0.125f;

    // scores: 16 lanes per row — coalesced LDG.128 (4 wavefronts/instr vs 32)
    {
        const int sub  = lane >> 4;    // row within warp pair
        const int ln16 = lane & 15;
        const float4 qv = *(const float4*)(qk_s + ln16*4);   // hoisted, reused
        #pragma unroll 5
        for (int t0 = warp*2 + sub; t0 < Tt; t0 += 8) {
            const float4 v = *(const float4*)(h + ((size_t)(b*Tt + t0))*MODEL + n*Dd + ln16*4);
            float p = v.x*qv.x + v.y*qv.y + v.z*qv.z + v.w*qv.w;
            p += __shfl_xor_sync(0xffffffffu, p, 8);
            p += __shfl_xor_sync(0xffffffffu, p, 4);
            p += __shfl_xor_sync(0xffffffffu, p, 2);
            p += __shfl_xor_sync(0xffffffffu, p, 1);
            if (ln16 == 0) {
                bool m;
                if (mask_int) m = ((const int*)mask)[b*Tt + t0] != 0;
                else          m = ((const unsigned char*)mask)[b*Tt + t0] != 0;
                s_s[t0] = m ? p * scale : -INFINITY;
            }
        }
    }
    __syncthreads();

    float lm = -INFINITY;
    for (int t = tid; t < Tt; t += 128) lm = fmaxf(lm, s_s[t]);
    #pragma unroll
    for (int off = 16; off; off >>= 1) lm = fmaxf(lm, __shfl_xor_sync(0xffffffffu, lm, off));
    if (lane == 0) red[warp] = lm;
    __syncthreads();
    const float mx = fmaxf(fmaxf(red[0], red[1]), fmaxf(red[2], red[3]));

    float ls = 0.0f;
    for (int t = tid; t < Tt; t += 128) {
        float e = __expf(s_s[t] - mx);
        s_s[t] = e;
        ls += e;
    }
    #pragma unroll
    for (int off = 16; off; off >>= 1) ls += __shfl_xor_sync(0xffffffffu, ls, off);
    __syncthreads();
    if (lane == 0) red[warp] = ls;
    __syncthreads();
    const float inv = 1.0f / (red[0] + red[1] + red[2] + red[3]);

    const int d2 = (tid & 31), chunk = tid >> 5;
    float2 acc = make_float2(0.f, 0.f);
    for (int t = chunk; t < Tt; t += 4) {
        const float w8 = s_s[t];
        const float2 v = *(const float2*)(h + ((size_t)(b*Tt + t))*MODEL + n*Dd + d2*2);
        acc.x = fmaf(w8, v.x, acc.x);
        acc.y = fmaf(w8, v.y, acc.y);
    }
    u_part[chunk][d2*2]   = acc.x;
    u_part[chunk][d2*2+1] = acc.y;
    __syncthreads();

    if (tid < 64) {
        qk_s[tid] = (u_part[0][tid] + u_part[1][tid] + u_part[2][tid] + u_part[3][tid]) * inv;
    }
    __syncthreads();
    if (tid < 64) {
        float c = 0.0f;
        const float* wvp = wv + (size_t)n*Dd*Dd + tid;
        #pragma unroll
        for (int dd = 0; dd < 64; dd++) c = fmaf(qk_s[dd], wvp[dd*Dd], c);
        out[((size_t)b*Nh + n)*Dd + tid] = c + q_s[tid];
    }
}

// ---------------- launch -------------------------------------------------------------
extern "C" void kernel_launch(void* const* d_in, const int* in_sizes, int n_in,
                              void* d_out, int out_size)
{
    const float* q    = (const float*)d_in[0];
    const float* seq  = (const float*)d_in[1];
    const float* rmsw = (const float*)d_in[2];
    const float* w1   = (const float*)d_in[3];
    const float* w2   = (const float*)d_in[4];
    const float* w3   = (const float*)d_in[5];
    const float* wk   = (const float*)d_in[6];
    const float* wv   = (const float*)d_in[7];
    const void*  msk  = d_in[8];
    float* out = (float*)d_out;

    __nv_bfloat16 *snb, *g, *w1b, *w2b, *w3b;
    float *h;
    cudaGetSymbolAddress((void**)&snb, d_snb);
    cudaGetSymbolAddress((void**)&g,   d_g);
    cudaGetSymbolAddress((void**)&h,   d_h);
    cudaGetSymbolAddress((void**)&w1b, d_w1b);
    cudaGetSymbolAddress((void**)&w2b, d_w2b);
    cudaGetSymbolAddress((void**)&w3b, d_w3b);

    const int SMEM = 98304;   // 96 KB per block, 2 blocks/SM
    cudaFuncSetAttribute(gemm_fused_kernel, cudaFuncAttributeMaxDynamicSharedMemorySize, SMEM);
    cudaFuncSetAttribute(gemm_out_kernel,   cudaFuncAttributeMaxDynamicSharedMemorySize, SMEM);

    prep_kernel<<<3072 + ROWS/8, 256>>>(w1, w2, w3, seq, rmsw, w1b, w2b, w3b, snb);

    cudaLaunchAttribute at[1];
    at[0].id = cudaLaunchAttributeProgrammaticStreamSerialization;
    at[0].val.programmaticStreamSerializationAllowed = 1;

    // GEMM1 with PDL (overlaps prep tail)
    {
        cudaLaunchConfig_t cfg = {};
        cfg.gridDim = dim3(FFNH/64, ROWS/128);
        cfg.blockDim = dim3(256);
        cfg.dynamicSmemBytes = SMEM;
        cfg.stream = 0;
        cfg.attrs = at;
        cfg.numAttrs = 1;
        cudaLaunchKernelEx(&cfg, gemm_fused_kernel, (const __nv_bfloat16*)snb,
                           (const __nv_bfloat16*)w1b, (const __nv_bfloat16*)w2b, g);
    }

    // GEMM2 with PDL (overlaps GEMM1 tail/epilogue)
    {
        cudaLaunchConfig_t cfg = {};
        cfg.gridDim = dim3(MODEL/128, ROWS/128);
        cfg.blockDim = dim3(256);
        cfg.dynamicSmemBytes = SMEM;
        cfg.stream = 0;
        cfg.attrs = at;
        cfg.numAttrs = 1;
        cudaLaunchKernelEx(&cfg, gemm_out_kernel, (const __nv_bfloat16*)g,
                           (const __nv_bfloat16*)w3b, seq, h);
    }

    // attn with PDL (mask/q/qk phase overlaps GEMM2 tail/epilogue)
    {
        cudaLaunchConfig_t cfg = {};
        cfg.gridDim = dim3(Nh, Bb);
        cfg.blockDim = dim3(128);
        cfg.dynamicSmemBytes = 0;
        cfg.stream = 0;
        cfg.attrs = at;
        cfg.numAttrs = 1;
        cudaLaunchKernelEx(&cfg, attn_kernel, q, (const float*)h, wk, wv, msk, out);
    }
}